// round 7
// baseline (speedup 1.0000x reference)
#include <cuda_runtime.h>

#define N_PTS 8192
#define D_TOK 384
#define KNN_K 16
#define KIN   387          // D_TOK + 3
#define KPAD  400          // padded K (multiple of 8)
#define NOUT  768          // [a | b] concatenated outputs
#define NCH   8
#define CHUNK (N_PTS / NCH)   // 1024
#define KT    8            // GEMM k-tile

#define FLT_BIG 3.402823e38f

typedef unsigned long long u64;

// ---------------- scratch (allocation-free rule: __device__ globals) --------
__device__ float g_Xp[N_PTS * KPAD];        // 13.1 MB padded node features
__device__ u64   g_Wp2[KPAD * NOUT];        //  2.5 MB packed-dup {w,w} weights
__device__ float g_C [N_PTS * NOUT];        // 25.2 MB [a_i | b_i]
__device__ int   g_knn[N_PTS * KNN_K];
__device__ float g_pd[N_PTS * NCH * KNN_K];
__device__ int   g_pi[N_PTS * NCH * KNN_K];

// ---------------- f32x2 helpers (Blackwell packed fp32) ---------------------
__device__ __forceinline__ void ffma2(u64& c, u64 a, u64 b) {
    asm("fma.rn.f32x2 %0, %1, %2, %0;" : "+l"(c) : "l"(a), "l"(b));
}
__device__ __forceinline__ u64 add2(u64 a, u64 b) {
    u64 r; asm("add.rn.f32x2 %0, %1, %2;" : "=l"(r) : "l"(a), "l"(b));
    return r;
}
__device__ __forceinline__ u64 pack2(float x) {
    u64 r; unsigned u = __float_as_uint(x);
    asm("mov.b64 %0, {%1, %1};" : "=l"(r) : "r"(u));
    return r;
}
__device__ __forceinline__ float lo32(u64 v) { return __uint_as_float((unsigned)v); }
__device__ __forceinline__ float hi32(u64 v) { return __uint_as_float((unsigned)(v >> 32)); }

// ---------------- pack kernels ---------------------------------------------
__global__ void pack_x(const float* __restrict__ token, const float* __restrict__ xyz)
{
    int i = blockIdx.x;
    for (int k = threadIdx.x; k < KPAD; k += blockDim.x) {
        float v;
        if (k < D_TOK)        v = token[i * D_TOK + k];
        else if (k < KIN)     v = xyz[i * 3 + (k - D_TOK)];
        else                  v = 0.f;
        g_Xp[i * KPAD + k] = v;
    }
}

__global__ void pack_w(const float* __restrict__ W1)
{
    int k = blockIdx.x;
    for (int n = threadIdx.x; n < NOUT; n += blockDim.x) {
        float v = 0.f;
        if (k < KIN) {
            if (n < D_TOK) v = W1[k * D_TOK + n];
            else           v = W1[(KIN + k) * D_TOK + (n - D_TOK)];
        }
        unsigned u = __float_as_uint(v);
        g_Wp2[k * NOUT + n] = ((u64)u << 32) | u;
    }
}

// ---------------- KNN -------------------------------------------------------
#define KNN_INSERT(dval, jval)                                              \
    do {                                                                    \
        if ((dval) < dmax) {                                                \
            _Pragma("unroll")                                               \
            for (int s_ = 0; s_ < KNN_K; s_++)                              \
                if (s_ == maxslot) { kd[s_] = (dval); ki[s_] = (jval); }    \
            dmax = -FLT_BIG; maxslot = 0;                                   \
            _Pragma("unroll")                                               \
            for (int s_ = 0; s_ < KNN_K; s_++)                              \
                if (kd[s_] > dmax) { dmax = kd[s_]; maxslot = s_; }         \
        }                                                                   \
    } while (0)

// packed f32x2: evaluate 2 candidates per instruction group
__global__ __launch_bounds__(256) void knn_partial(const float* __restrict__ xyz)
{
    __shared__ float4 sA4[128];    // per pair: {x0,x1,y0,y1}
    __shared__ float4 sB4[128];    // per pair: {z0,z1,q0,q1}
    float* sA = (float*)sA4;
    float* sB = (float*)sB4;

    int tidx  = threadIdx.x;
    int q     = blockIdx.x * 256 + tidx;
    int chunk = blockIdx.y;

    float xi = xyz[3 * q], yi = xyz[3 * q + 1], zi = xyz[3 * q + 2];
    float sqi = xi * xi + yi * yi + zi * zi;
    u64 sqi2 = pack2(sqi);
    u64 nx2  = pack2(-2.f * xi);
    u64 ny2  = pack2(-2.f * yi);
    u64 nz2  = pack2(-2.f * zi);

    float kd[KNN_K]; int ki[KNN_K];
    #pragma unroll
    for (int s = 0; s < KNN_K; s++) { kd[s] = FLT_BIG; ki[s] = 0; }
    float dmax = FLT_BIG; int maxslot = 0;

    int base = chunk * CHUNK;
    for (int t0 = 0; t0 < CHUNK; t0 += 256) {
        int j = base + t0 + tidx;
        __syncthreads();
        float px = xyz[3 * j], py = xyz[3 * j + 1], pz = xyz[3 * j + 2];
        float qn = px * px + py * py + pz * pz;
        int pr = tidx >> 1, h = tidx & 1;
        sA[pr * 4 + h]     = px;
        sA[pr * 4 + 2 + h] = py;
        sB[pr * 4 + h]     = pz;
        sB[pr * 4 + 2 + h] = qn;
        __syncthreads();

        const ulonglong2* A2 = (const ulonglong2*)sA4;
        const ulonglong2* B2 = (const ulonglong2*)sB4;
        #pragma unroll 4
        for (int p = 0; p < 128; p++) {
            ulonglong2 a = A2[p];      // a.x={x0,x1}  a.y={y0,y1}
            ulonglong2 b = B2[p];      // b.x={z0,z1}  b.y={q0,q1}
            u64 d2 = add2(sqi2, b.y);
            ffma2(d2, nx2, a.x);
            ffma2(d2, ny2, a.y);
            ffma2(d2, nz2, b.x);
            float dlo = lo32(d2), dhi = hi32(d2);
            if (fminf(dlo, dhi) < dmax) {        // rare after warm-up
                int j0 = base + t0 + 2 * p;
                if (j0 != q)     KNN_INSERT(dlo, j0);
                if (j0 + 1 != q) KNN_INSERT(dhi, j0 + 1);
            }
        }
    }
    int ob = (q * NCH + chunk) * KNN_K;
    #pragma unroll
    for (int s = 0; s < KNN_K; s++) { g_pd[ob + s] = kd[s]; g_pi[ob + s] = ki[s]; }
}

// warp-per-query merge: 128 candidate keys -> top-16 via min-extraction
__global__ __launch_bounds__(256) void knn_merge()
{
    int warp = (blockIdx.x * blockDim.x + threadIdx.x) >> 5;
    int lane = threadIdx.x & 31;
    const int E   = NCH * KNN_K;     // 128
    const int PER = E / 32;          // 4

    u64 key[PER];
    int ob = warp * E;
    #pragma unroll
    for (int t = 0; t < PER; t++) {
        int e = lane + 32 * t;
        float d = fmaxf(g_pd[ob + e], 0.f);     // keep bits-order == value-order
        unsigned idx = (unsigned)g_pi[ob + e];
        key[t] = ((u64)__float_as_uint(d) << 32) | idx;
    }

    int myidx = 0;
    #pragma unroll
    for (int r = 0; r < KNN_K; r++) {
        u64 m = key[0];
        #pragma unroll
        for (int t = 1; t < PER; t++) m = (key[t] < m) ? key[t] : m;
        #pragma unroll
        for (int off = 16; off > 0; off >>= 1) {
            u64 o = __shfl_xor_sync(0xFFFFFFFFu, m, off);
            m = (o < m) ? o : m;
        }
        if (r == lane) myidx = (int)(unsigned)(m & 0xFFFFFFFFull);
        #pragma unroll
        for (int t = 0; t < PER; t++)
            if (key[t] == m) key[t] = ~0ull;
    }
    if (lane < KNN_K) g_knn[warp * KNN_K + lane] = myidx;
}

// ---------------- node GEMM: C[8192,768] = Xp @ W (+b1 on first 384) -------
// M-pair packed accumulators (acc[4][8] u64), B pre-duplicated {w,w} so the
// inner loop is pure LDS.64 (broadcast A-pairs, conflict-free strided B).
__global__ __launch_bounds__(256, 2) void gemm_kernel(const float* __restrict__ b1)
{
    __shared__ float As[2][KT][132];   // [k][m], m-pairs contiguous
    __shared__ u64   Bs[2][KT][128];   // [k][n], each entry {w,w}

    int tid = threadIdx.x;
    int bm = blockIdx.y, bn = blockIdx.x;

    const float* Ab = g_Xp  + bm * 128 * KPAD;
    const u64*   Bb = g_Wp2 + bn * 128;

    int aRow = tid >> 1, aCol = (tid & 1) << 2;   // A: 128 rows x 8 cols
    int bRow = tid >> 5, bCol = (tid & 31) << 2;  // B: 8 rows x 128 u64
    int ty = tid >> 4, tx = tid & 15;

    u64 acc[4][8];
    #pragma unroll
    for (int i = 0; i < 4; i++)
        #pragma unroll
        for (int j = 0; j < 8; j++) acc[i][j] = 0ull;

    auto loadTiles = [&](int buf, int k0) {
        float4 v = *(const float4*)(Ab + aRow * KPAD + k0 + aCol);
        As[buf][aCol + 0][aRow] = v.x;
        As[buf][aCol + 1][aRow] = v.y;
        As[buf][aCol + 2][aRow] = v.z;
        As[buf][aCol + 3][aRow] = v.w;
        ulonglong2 w0 = *(const ulonglong2*)(Bb + (k0 + bRow) * NOUT + bCol);
        ulonglong2 w1 = *(const ulonglong2*)(Bb + (k0 + bRow) * NOUT + bCol + 2);
        *(ulonglong2*)&Bs[buf][bRow][bCol]     = w0;
        *(ulonglong2*)&Bs[buf][bRow][bCol + 2] = w1;
    };

    loadTiles(0, 0);
    __syncthreads();

    const int NT = KPAD / KT;   // 50
    for (int t = 0; t < NT; t++) {
        if (t + 1 < NT) loadTiles((t + 1) & 1, (t + 1) * KT);
        int cb = t & 1;
        #pragma unroll
        for (int k = 0; k < KT; k++) {
            u64 rm[4], rn[8];
            #pragma unroll
            for (int mi = 0; mi < 4; mi++)
                rm[mi] = *(const u64*)&As[cb][k][ty * 8 + 2 * mi];   // broadcast
            #pragma unroll
            for (int nj = 0; nj < 8; nj++)
                rn[nj] = Bs[cb][k][tx + 16 * nj];                    // conflict-free
            #pragma unroll
            for (int mi = 0; mi < 4; mi++)
                #pragma unroll
                for (int nj = 0; nj < 8; nj++)
                    ffma2(acc[mi][nj], rm[mi], rn[nj]);
        }
        __syncthreads();
    }

    // epilogue: thread owns rows rowBase..rowBase+7, cols colTx + 16*nj
    int colTx   = bn * 128 + tx;
    int rowBase = bm * 128 + ty * 8;
    bool hasB = (bn < 3);
    float bias[8];
    #pragma unroll
    for (int nj = 0; nj < 8; nj++) bias[nj] = hasB ? b1[colTx + 16 * nj] : 0.f;

    #pragma unroll
    for (int mi = 0; mi < 4; mi++) {
        int r0 = rowBase + 2 * mi;
        #pragma unroll
        for (int nj = 0; nj < 8; nj++) {
            int col = colTx + 16 * nj;
            g_C[r0 * NOUT + col]       = lo32(acc[mi][nj]) + bias[nj];
            g_C[(r0 + 1) * NOUT + col] = hi32(acc[mi][nj]) + bias[nj];
        }
    }
}

// ---------------- edge kernel: one warp per node ----------------------------
__global__ __launch_bounds__(256) void edge_kernel(const float* __restrict__ xyz,
                                                   const float* __restrict__ W2,
                                                   const float* __restrict__ b2,
                                                   float* __restrict__ out)
{
    int gwarp = (blockIdx.x * blockDim.x + threadIdx.x) >> 5;
    int lane  = threadIdx.x & 31;
    if (gwarp >= N_PTS) return;

    const float* Ci = g_C + gwarp * NOUT;

    float4 s[3];
    float w2[12][3];
    #pragma unroll
    for (int dn = 0; dn < 3; dn++) {
        int dim0 = lane * 4 + dn * 128;
        float4 a = *(const float4*)(Ci + dim0);           // a_i (has b1)
        float4 b = *(const float4*)(Ci + D_TOK + dim0);   // b_i
        s[dn] = make_float4(a.x - b.x, a.y - b.y, a.z - b.z, a.w - b.w);
        #pragma unroll
        for (int u = 0; u < 4; u++)
            #pragma unroll
            for (int c = 0; c < 3; c++)
                w2[dn * 4 + u][c] = W2[(dim0 + u) * 3 + c];
    }

    float acc0 = 0.f, acc1 = 0.f, acc2 = 0.f;
    #pragma unroll 4
    for (int j = 0; j < KNN_K; j++) {
        int nj = g_knn[gwarp * KNN_K + j];
        const float* Bj = g_C + nj * NOUT + D_TOK;
        #pragma unroll
        for (int dn = 0; dn < 3; dn++) {
            float4 b = *(const float4*)(Bj + lane * 4 + dn * 128);
            float h;
            h = fmaxf(s[dn].x + b.x, 0.f);
            acc0 = fmaf(h, w2[dn*4+0][0], acc0); acc1 = fmaf(h, w2[dn*4+0][1], acc1); acc2 = fmaf(h, w2[dn*4+0][2], acc2);
            h = fmaxf(s[dn].y + b.y, 0.f);
            acc0 = fmaf(h, w2[dn*4+1][0], acc0); acc1 = fmaf(h, w2[dn*4+1][1], acc1); acc2 = fmaf(h, w2[dn*4+1][2], acc2);
            h = fmaxf(s[dn].z + b.z, 0.f);
            acc0 = fmaf(h, w2[dn*4+2][0], acc0); acc1 = fmaf(h, w2[dn*4+2][1], acc1); acc2 = fmaf(h, w2[dn*4+2][2], acc2);
            h = fmaxf(s[dn].w + b.w, 0.f);
            acc0 = fmaf(h, w2[dn*4+3][0], acc0); acc1 = fmaf(h, w2[dn*4+3][1], acc1); acc2 = fmaf(h, w2[dn*4+3][2], acc2);
        }
    }

    #pragma unroll
    for (int off = 16; off > 0; off >>= 1) {
        acc0 += __shfl_down_sync(0xFFFFFFFFu, acc0, off);
        acc1 += __shfl_down_sync(0xFFFFFFFFu, acc1, off);
        acc2 += __shfl_down_sync(0xFFFFFFFFu, acc2, off);
    }

    if (lane == 0) {
        const float inv = 1.f / 16.f;
        out[gwarp * 3 + 0] = xyz[gwarp * 3 + 0] + acc0 * inv + b2[0];
        out[gwarp * 3 + 1] = xyz[gwarp * 3 + 1] + acc1 * inv + b2[1];
        out[gwarp * 3 + 2] = xyz[gwarp * 3 + 2] + acc2 * inv + b2[2];
    }
}

// ---------------- launch ----------------------------------------------------
// knn_partial at stream position 3 — the launch ncu captures — so next round
// we get its metrics. gemm only depends on the two pack kernels.
extern "C" void kernel_launch(void* const* d_in, const int* in_sizes, int n_in,
                              void* d_out, int out_size)
{
    const float* xyz   = (const float*)d_in[0];
    const float* token = (const float*)d_in[1];
    const float* W1    = (const float*)d_in[2];
    const float* b1    = (const float*)d_in[3];
    const float* W2    = (const float*)d_in[4];
    const float* b2    = (const float*)d_in[5];
    float* out = (float*)d_out;

    pack_x<<<N_PTS, 128>>>(token, xyz);
    pack_w<<<KPAD, 256>>>(W1);
    gemm_kernel<<<dim3(NOUT / 128, N_PTS / 128), 256>>>(b1);
    knn_partial<<<dim3(N_PTS / 256, NCH), 256>>>(xyz);
    knn_merge<<<(N_PTS * 32) / 256, 256>>>();
    edge_kernel<<<N_PTS / 8, 256>>>(xyz, W2, b2, out);
}

// round 8
// speedup vs baseline: 2.7416x; 2.7416x over previous
#include <cuda_runtime.h>

#define N_PTS 8192
#define D_TOK 384
#define KNN_K 16
#define KIN   387          // D_TOK + 3
#define KPAD  400          // padded K (multiple of 8)
#define NOUT  768          // [a | b] concatenated outputs
#define KT    8            // GEMM k-tile
#define TILE  1024         // KNN candidate tile (smem)

#define FLT_BIG 3.402823e38f

typedef unsigned long long u64;

// ---------------- scratch (allocation-free rule: __device__ globals) --------
__device__ float  g_Xp[N_PTS * KPAD];        // 13.1 MB padded node features
__device__ u64    g_Wp2[KPAD * NOUT];        //  2.5 MB packed-dup {w,w} weights
__device__ float  g_C [N_PTS * NOUT];        // 25.2 MB [a_i | b_i]
__device__ int    g_knn[N_PTS * KNN_K];
__device__ float4 g_P [N_PTS];               // {x, y, z, |p|^2}

// ---------------- f32x2 helpers (Blackwell packed fp32) ---------------------
__device__ __forceinline__ void ffma2(u64& c, u64 a, u64 b) {
    asm("fma.rn.f32x2 %0, %1, %2, %0;" : "+l"(c) : "l"(a), "l"(b));
}
__device__ __forceinline__ float lo32(u64 v) { return __uint_as_float((unsigned)v); }
__device__ __forceinline__ float hi32(u64 v) { return __uint_as_float((unsigned)(v >> 32)); }

// ---------------- pack kernels ---------------------------------------------
__global__ void pack_p(const float* __restrict__ xyz)
{
    int i = blockIdx.x * 256 + threadIdx.x;
    if (i < N_PTS) {
        float x = xyz[3 * i], y = xyz[3 * i + 1], z = xyz[3 * i + 2];
        g_P[i] = make_float4(x, y, z, x * x + y * y + z * z);
    }
}

__global__ void pack_x(const float* __restrict__ token, const float* __restrict__ xyz)
{
    int i = blockIdx.x;
    for (int k = threadIdx.x; k < KPAD; k += blockDim.x) {
        float v;
        if (k < D_TOK)        v = token[i * D_TOK + k];
        else if (k < KIN)     v = xyz[i * 3 + (k - D_TOK)];
        else                  v = 0.f;
        g_Xp[i * KPAD + k] = v;
    }
}

__global__ void pack_w(const float* __restrict__ W1)
{
    int k = blockIdx.x;
    for (int n = threadIdx.x; n < NOUT; n += blockDim.x) {
        float v = 0.f;
        if (k < KIN) {
            if (n < D_TOK) v = W1[k * D_TOK + n];
            else           v = W1[(KIN + k) * D_TOK + (n - D_TOK)];
        }
        unsigned u = __float_as_uint(v);
        g_Wp2[k * NOUT + n] = ((u64)u << 32) | u;
    }
}

// ---------------- KNN: warp-per-query, distributed sorted top-16 ------------
// Lanes 0..15 hold the sorted (ascending) top-16 as u64 keys
// (monotone_float_bits(dist) << 32) | index. Fast path is branch-free:
// 9 warp-instructions per 32 candidates + one ballot. Inserts are
// warp-collective shift-inserts, gated twice (float threshold, then exact
// u64 key compare), so the divergent body runs only ~200x per query.
__global__ __launch_bounds__(256) void knn_warp()
{
    __shared__ float4 sP[TILE];     // 16 KB
    int lane = threadIdx.x & 31;
    int wid  = threadIdx.x >> 5;
    int q    = blockIdx.x * 8 + wid;

    float4 Q = g_P[q];
    float sqi = Q.w;
    float nx = -2.f * Q.x, ny = -2.f * Q.y, nz = -2.f * Q.z;

    u64   mykey = ~0ull;     // lanes 0..15: sorted list; others unused
    u64   Tkey  = ~0ull;     // key of current 16th-best (lane 15), broadcast
    float Td    = FLT_BIG;   // its distance, for the fast-path compare

    for (int t0 = 0; t0 < N_PTS; t0 += TILE) {
        __syncthreads();
        #pragma unroll
        for (int i = 0; i < TILE / 256; i++)
            sP[threadIdx.x + 256 * i] = g_P[t0 + threadIdx.x + 256 * i];
        __syncthreads();

        #pragma unroll 4
        for (int s = 0; s < TILE / 32; s++) {
            float4 c = sP[s * 32 + lane];
            float d = sqi + c.w;
            d = fmaf(nx, c.x, d);
            d = fmaf(ny, c.y, d);
            d = fmaf(nz, c.z, d);
            unsigned bal = __ballot_sync(0xFFFFFFFFu, d <= Td);
            while (bal) {                        // uniform across warp
                int src = __ffs(bal) - 1;
                bal &= bal - 1;
                float dd = __shfl_sync(0xFFFFFFFFu, d, src);
                int jj = t0 + s * 32 + src;
                if (jj != q) {
                    unsigned b = __float_as_uint(dd);
                    unsigned m = b ^ (unsigned)(((int)b >> 31) | 0x80000000);
                    u64 k = ((u64)m << 32) | (unsigned)jj;
                    if (k < Tkey) {
                        bool less = mykey > k;
                        unsigned ib = __ballot_sync(0xFFFFFFFFu, less) & 0xFFFFu;
                        int pos = 16 - __popc(ib);
                        u64 up = __shfl_up_sync(0xFFFFFFFFu, mykey, 1);
                        if (lane < 16 && less)
                            mykey = (lane == pos) ? k : up;
                        Tkey = __shfl_sync(0xFFFFFFFFu, mykey, 15);
                        unsigned hi = (unsigned)(Tkey >> 32);
                        unsigned fb = (hi & 0x80000000u) ? (hi ^ 0x80000000u) : ~hi;
                        Td = __uint_as_float(fb);
                    }
                }
            }
        }
    }
    if (lane < KNN_K)
        g_knn[q * KNN_K + lane] = (int)(unsigned)(mykey & 0xFFFFFFFFull);
}

// ---------------- node GEMM: C[8192,768] = Xp @ W (+b1 on first 384) -------
// M-pair packed accumulators (acc[4][8] u64), B pre-duplicated {w,w} so the
// inner loop is pure LDS.64 (broadcast A-pairs, conflict-free strided B).
__global__ __launch_bounds__(256, 2) void gemm_kernel(const float* __restrict__ b1)
{
    __shared__ float As[2][KT][132];   // [k][m], m-pairs contiguous
    __shared__ u64   Bs[2][KT][128];   // [k][n], each entry {w,w}

    int tid = threadIdx.x;
    int bm = blockIdx.y, bn = blockIdx.x;

    const float* Ab = g_Xp  + bm * 128 * KPAD;
    const u64*   Bb = g_Wp2 + bn * 128;

    int aRow = tid >> 1, aCol = (tid & 1) << 2;   // A: 128 rows x 8 cols
    int bRow = tid >> 5, bCol = (tid & 31) << 2;  // B: 8 rows x 128 u64
    int ty = tid >> 4, tx = tid & 15;

    u64 acc[4][8];
    #pragma unroll
    for (int i = 0; i < 4; i++)
        #pragma unroll
        for (int j = 0; j < 8; j++) acc[i][j] = 0ull;

    auto loadTiles = [&](int buf, int k0) {
        float4 v = *(const float4*)(Ab + aRow * KPAD + k0 + aCol);
        As[buf][aCol + 0][aRow] = v.x;
        As[buf][aCol + 1][aRow] = v.y;
        As[buf][aCol + 2][aRow] = v.z;
        As[buf][aCol + 3][aRow] = v.w;
        ulonglong2 w0 = *(const ulonglong2*)(Bb + (k0 + bRow) * NOUT + bCol);
        ulonglong2 w1 = *(const ulonglong2*)(Bb + (k0 + bRow) * NOUT + bCol + 2);
        *(ulonglong2*)&Bs[buf][bRow][bCol]     = w0;
        *(ulonglong2*)&Bs[buf][bRow][bCol + 2] = w1;
    };

    loadTiles(0, 0);
    __syncthreads();

    const int NT = KPAD / KT;   // 50
    for (int t = 0; t < NT; t++) {
        if (t + 1 < NT) loadTiles((t + 1) & 1, (t + 1) * KT);
        int cb = t & 1;
        #pragma unroll
        for (int k = 0; k < KT; k++) {
            u64 rm[4], rn[8];
            #pragma unroll
            for (int mi = 0; mi < 4; mi++)
                rm[mi] = *(const u64*)&As[cb][k][ty * 8 + 2 * mi];   // broadcast
            #pragma unroll
            for (int nj = 0; nj < 8; nj++)
                rn[nj] = Bs[cb][k][tx + 16 * nj];                    // conflict-free
            #pragma unroll
            for (int mi = 0; mi < 4; mi++)
                #pragma unroll
                for (int nj = 0; nj < 8; nj++)
                    ffma2(acc[mi][nj], rm[mi], rn[nj]);
        }
        __syncthreads();
    }

    int colTx   = bn * 128 + tx;
    int rowBase = bm * 128 + ty * 8;
    bool hasB = (bn < 3);
    float bias[8];
    #pragma unroll
    for (int nj = 0; nj < 8; nj++) bias[nj] = hasB ? b1[colTx + 16 * nj] : 0.f;

    #pragma unroll
    for (int mi = 0; mi < 4; mi++) {
        int r0 = rowBase + 2 * mi;
        #pragma unroll
        for (int nj = 0; nj < 8; nj++) {
            int col = colTx + 16 * nj;
            g_C[r0 * NOUT + col]       = lo32(acc[mi][nj]) + bias[nj];
            g_C[(r0 + 1) * NOUT + col] = hi32(acc[mi][nj]) + bias[nj];
        }
    }
}

// ---------------- edge kernel: one warp per node ----------------------------
__global__ __launch_bounds__(256) void edge_kernel(const float* __restrict__ xyz,
                                                   const float* __restrict__ W2,
                                                   const float* __restrict__ b2,
                                                   float* __restrict__ out)
{
    int gwarp = (blockIdx.x * blockDim.x + threadIdx.x) >> 5;
    int lane  = threadIdx.x & 31;
    if (gwarp >= N_PTS) return;

    const float* Ci = g_C + gwarp * NOUT;

    float4 s[3];
    float w2[12][3];
    #pragma unroll
    for (int dn = 0; dn < 3; dn++) {
        int dim0 = lane * 4 + dn * 128;
        float4 a = *(const float4*)(Ci + dim0);           // a_i (has b1)
        float4 b = *(const float4*)(Ci + D_TOK + dim0);   // b_i
        s[dn] = make_float4(a.x - b.x, a.y - b.y, a.z - b.z, a.w - b.w);
        #pragma unroll
        for (int u = 0; u < 4; u++)
            #pragma unroll
            for (int c = 0; c < 3; c++)
                w2[dn * 4 + u][c] = W2[(dim0 + u) * 3 + c];
    }

    float acc0 = 0.f, acc1 = 0.f, acc2 = 0.f;
    #pragma unroll 4
    for (int j = 0; j < KNN_K; j++) {
        int nj = g_knn[gwarp * KNN_K + j];
        const float* Bj = g_C + nj * NOUT + D_TOK;
        #pragma unroll
        for (int dn = 0; dn < 3; dn++) {
            float4 b = *(const float4*)(Bj + lane * 4 + dn * 128);
            float h;
            h = fmaxf(s[dn].x + b.x, 0.f);
            acc0 = fmaf(h, w2[dn*4+0][0], acc0); acc1 = fmaf(h, w2[dn*4+0][1], acc1); acc2 = fmaf(h, w2[dn*4+0][2], acc2);
            h = fmaxf(s[dn].y + b.y, 0.f);
            acc0 = fmaf(h, w2[dn*4+1][0], acc0); acc1 = fmaf(h, w2[dn*4+1][1], acc1); acc2 = fmaf(h, w2[dn*4+1][2], acc2);
            h = fmaxf(s[dn].z + b.z, 0.f);
            acc0 = fmaf(h, w2[dn*4+2][0], acc0); acc1 = fmaf(h, w2[dn*4+2][1], acc1); acc2 = fmaf(h, w2[dn*4+2][2], acc2);
            h = fmaxf(s[dn].w + b.w, 0.f);
            acc0 = fmaf(h, w2[dn*4+3][0], acc0); acc1 = fmaf(h, w2[dn*4+3][1], acc1); acc2 = fmaf(h, w2[dn*4+3][2], acc2);
        }
    }

    #pragma unroll
    for (int off = 16; off > 0; off >>= 1) {
        acc0 += __shfl_down_sync(0xFFFFFFFFu, acc0, off);
        acc1 += __shfl_down_sync(0xFFFFFFFFu, acc1, off);
        acc2 += __shfl_down_sync(0xFFFFFFFFu, acc2, off);
    }

    if (lane == 0) {
        const float inv = 1.f / 16.f;
        out[gwarp * 3 + 0] = xyz[gwarp * 3 + 0] + acc0 * inv + b2[0];
        out[gwarp * 3 + 1] = xyz[gwarp * 3 + 1] + acc1 * inv + b2[1];
        out[gwarp * 3 + 2] = xyz[gwarp * 3 + 2] + acc2 * inv + b2[2];
    }
}

// ---------------- launch ----------------------------------------------------
// knn_warp at stream position 4 (the launch ncu captures) so next round we
// verify the new selection algorithm directly.
extern "C" void kernel_launch(void* const* d_in, const int* in_sizes, int n_in,
                              void* d_out, int out_size)
{
    const float* xyz   = (const float*)d_in[0];
    const float* token = (const float*)d_in[1];
    const float* W1    = (const float*)d_in[2];
    const float* b1    = (const float*)d_in[3];
    const float* W2    = (const float*)d_in[4];
    const float* b2    = (const float*)d_in[5];
    float* out = (float*)d_out;

    pack_p<<<N_PTS / 256, 256>>>(xyz);
    pack_x<<<N_PTS, 128>>>(token, xyz);
    pack_w<<<KPAD, 256>>>(W1);
    knn_warp<<<N_PTS / 8, 256>>>();
    gemm_kernel<<<dim3(NOUT / 128, N_PTS / 128), 256>>>(b1);
    edge_kernel<<<N_PTS / 8, 256>>>(xyz, W2, b2, out);
}

// round 9
// speedup vs baseline: 4.3997x; 1.6048x over previous
#include <cuda_runtime.h>
#include <cuda_bf16.h>

#define N_PTS 8192
#define D_TOK 384
#define KNN_K 16
#define KIN   387            // D_TOK + 3
#define KPAD  400            // padded K (multiple of 16)
#define KP2   (KPAD / 2)     // 200 k-pairs
#define NOUT  768            // [a | b] concatenated outputs
#define TILE  1024           // KNN candidate tile (smem)
#define STAGES (KPAD / 16)   // 25 gemm k-stages

#define FLT_BIG 3.402823e38f

typedef unsigned long long u64;
typedef unsigned u32;

// ---------------- scratch (allocation-free rule: __device__ globals) --------
__device__ u32    g_AH[N_PTS * KP2];     // bf16x2-packed hi(X)  6.6 MB
__device__ u32    g_AL[N_PTS * KP2];     // bf16x2-packed lo(X)  6.6 MB
__device__ u32    g_BH[KP2 * NOUT];      // bf16x2-packed hi(W)  0.6 MB
__device__ u32    g_BL[KP2 * NOUT];      // bf16x2-packed lo(W)  0.6 MB
__device__ float  g_C [N_PTS * NOUT];    // 25.2 MB [a_i | b_i]
__device__ int    g_knn[N_PTS * KNN_K];
__device__ float4 g_P [N_PTS];           // {x, y, z, |p|^2}

// ---------------- bf16 split helpers ----------------------------------------
__device__ __forceinline__ u32 pack_hi_lo(float v0, float v1, bool lo)
{
    __nv_bfloat16 h0 = __float2bfloat16(v0);
    __nv_bfloat16 h1 = __float2bfloat16(v1);
    if (lo) {
        h0 = __float2bfloat16(v0 - __bfloat162float(h0));
        h1 = __float2bfloat16(v1 - __bfloat162float(h1));
    }
    __nv_bfloat162 p = __nv_bfloat162(h0, h1);   // x = low half (even k)
    return *reinterpret_cast<u32*>(&p);
}

__device__ __forceinline__ void mma_bf16(float* c, const u32* a, u32 b0, u32 b1)
{
    asm volatile(
        "mma.sync.aligned.m16n8k16.row.col.f32.bf16.bf16.f32 "
        "{%0,%1,%2,%3}, {%4,%5,%6,%7}, {%8,%9}, {%0,%1,%2,%3};\n"
        : "+f"(c[0]), "+f"(c[1]), "+f"(c[2]), "+f"(c[3])
        : "r"(a[0]), "r"(a[1]), "r"(a[2]), "r"(a[3]), "r"(b0), "r"(b1));
}

// ---------------- pack kernels ---------------------------------------------
__global__ void pack_p(const float* __restrict__ xyz)
{
    int i = blockIdx.x * 256 + threadIdx.x;
    if (i < N_PTS) {
        float x = xyz[3 * i], y = xyz[3 * i + 1], z = xyz[3 * i + 2];
        g_P[i] = make_float4(x, y, z, x * x + y * y + z * z);
    }
}

__device__ __forceinline__ float xval(const float* token, const float* xyz, int i, int k)
{
    if (k < D_TOK) return token[i * D_TOK + k];
    if (k < KIN)   return xyz[i * 3 + (k - D_TOK)];
    return 0.f;
}

__global__ void pack_x(const float* __restrict__ token, const float* __restrict__ xyz)
{
    int i = blockIdx.x;
    for (int kp = threadIdx.x; kp < KP2; kp += blockDim.x) {
        float v0 = xval(token, xyz, i, 2 * kp);
        float v1 = xval(token, xyz, i, 2 * kp + 1);
        g_AH[i * KP2 + kp] = pack_hi_lo(v0, v1, false);
        g_AL[i * KP2 + kp] = pack_hi_lo(v0, v1, true);
    }
}

__device__ __forceinline__ float wval(const float* W1, int k, int n)
{
    if (k >= KIN) return 0.f;
    if (n < D_TOK) return W1[k * D_TOK + n];
    return W1[(KIN + k) * D_TOK + (n - D_TOK)];
}

__global__ void pack_w(const float* __restrict__ W1)
{
    int kp = blockIdx.x;              // 0..KP2-1
    for (int n = threadIdx.x; n < NOUT; n += blockDim.x) {
        float v0 = wval(W1, 2 * kp, n);
        float v1 = wval(W1, 2 * kp + 1, n);
        g_BH[kp * NOUT + n] = pack_hi_lo(v0, v1, false);
        g_BL[kp * NOUT + n] = pack_hi_lo(v0, v1, true);
    }
}

// ---------------- KNN: warp-per-query, distributed sorted top-16 ------------
__global__ __launch_bounds__(256) void knn_warp()
{
    __shared__ float4 sP[TILE];     // 16 KB
    int lane = threadIdx.x & 31;
    int wid  = threadIdx.x >> 5;
    int q    = blockIdx.x * 8 + wid;

    float4 Q = g_P[q];
    float sqi = Q.w;
    float nx = -2.f * Q.x, ny = -2.f * Q.y, nz = -2.f * Q.z;

    u64   mykey = ~0ull;     // lanes 0..15: sorted list; others unused
    u64   Tkey  = ~0ull;     // key of current 16th-best (lane 15), broadcast
    float Td    = FLT_BIG;

    for (int t0 = 0; t0 < N_PTS; t0 += TILE) {
        __syncthreads();
        #pragma unroll
        for (int i = 0; i < TILE / 256; i++)
            sP[threadIdx.x + 256 * i] = g_P[t0 + threadIdx.x + 256 * i];
        __syncthreads();

        #pragma unroll 4
        for (int s = 0; s < TILE / 32; s++) {
            float4 c = sP[s * 32 + lane];
            float d = sqi + c.w;
            d = fmaf(nx, c.x, d);
            d = fmaf(ny, c.y, d);
            d = fmaf(nz, c.z, d);
            unsigned bal = __ballot_sync(0xFFFFFFFFu, d <= Td);
            while (bal) {                        // uniform across warp
                int src = __ffs(bal) - 1;
                bal &= bal - 1;
                float dd = __shfl_sync(0xFFFFFFFFu, d, src);
                int jj = t0 + s * 32 + src;
                if (jj != q) {
                    unsigned b = __float_as_uint(dd);
                    unsigned m = b ^ (unsigned)(((int)b >> 31) | 0x80000000);
                    u64 k = ((u64)m << 32) | (unsigned)jj;
                    if (k < Tkey) {
                        bool less = mykey > k;
                        unsigned ib = __ballot_sync(0xFFFFFFFFu, less) & 0xFFFFu;
                        int pos = 16 - __popc(ib);
                        u64 up = __shfl_up_sync(0xFFFFFFFFu, mykey, 1);
                        if (lane < 16 && less)
                            mykey = (lane == pos) ? k : up;
                        Tkey = __shfl_sync(0xFFFFFFFFu, mykey, 15);
                        unsigned hi = (unsigned)(Tkey >> 32);
                        unsigned fb = (hi & 0x80000000u) ? (hi ^ 0x80000000u) : ~hi;
                        Td = __uint_as_float(fb);
                    }
                }
            }
        }
    }
    if (lane < KNN_K)
        g_knn[q * KNN_K + lane] = (int)(unsigned)(mykey & 0xFFFFFFFFull);
}

// ---------------- node GEMM via bf16 tensor cores (3-MMA split) -------------
// C[8192,768] = X @ W (+b1 on cols<384), X/W split as hi+lo bf16:
//   C ~= Xh*Wh + Xh*Wl + Xl*Wh   (error ~2^-18 relative)
// Block 128x128, 8 warps of 32x64, k-step 16 (8 bf16x2 k-pairs), double-buffer.
__global__ __launch_bounds__(256, 2) void gemm_kernel(const float* __restrict__ b1)
{
    __shared__ u32 Ah[2][128][12];   // [buf][m][kpair], ld 12 (pad, conflict-free)
    __shared__ u32 Al[2][128][12];
    __shared__ u32 Bh[2][8][136];    // [buf][kpair][n],  ld 136 (conflict-free)
    __shared__ u32 Bl[2][8][136];

    int tid = threadIdx.x;
    int bm = blockIdx.y, bn = blockIdx.x;
    int wid = tid >> 5, lane = tid & 31;
    int wm = wid & 3, wn = wid >> 2;            // warp tile (wm*32, wn*64)
    int g = lane >> 2, t = lane & 3;

    // global load coords (per stage)
    int arow = tid >> 1, ah4 = (tid & 1) << 2;  // A: 128 rows x 8 u32 (2 uint4)
    int brow = tid >> 5, bc4 = (tid & 31) << 2; // B: 8 rows x 128 u32

    const u32* Agh = g_AH + (bm * 128 + arow) * KP2 + ah4;
    const u32* Agl = g_AL + (bm * 128 + arow) * KP2 + ah4;
    const u32* Bgh = g_BH + brow * NOUT + bn * 128 + bc4;
    const u32* Bgl = g_BL + brow * NOUT + bn * 128 + bc4;

    float acc[2][8][4];
    #pragma unroll
    for (int i = 0; i < 2; i++)
        #pragma unroll
        for (int j = 0; j < 8; j++)
            #pragma unroll
            for (int r = 0; r < 4; r++) acc[i][j][r] = 0.f;

    // stage 0 direct to smem
    {
        uint4 vah = *(const uint4*)(Agh);
        uint4 val = *(const uint4*)(Agl);
        uint4 vbh = *(const uint4*)(Bgh);
        uint4 vbl = *(const uint4*)(Bgl);
        *(uint4*)&Ah[0][arow][ah4] = vah;
        *(uint4*)&Al[0][arow][ah4] = val;
        *(uint4*)&Bh[0][brow][bc4] = vbh;
        *(uint4*)&Bl[0][brow][bc4] = vbl;
    }
    __syncthreads();

    for (int s = 0; s < STAGES; s++) {
        int cur = s & 1;
        uint4 vah, val, vbh, vbl;
        if (s + 1 < STAGES) {
            int kp = (s + 1) * 8;
            vah = *(const uint4*)(Agh + kp);
            val = *(const uint4*)(Agl + kp);
            vbh = *(const uint4*)(Bgh + kp * NOUT);
            vbl = *(const uint4*)(Bgl + kp * NOUT);
        }

        // ---- compute on cur ----
        u32 fah[2][4], fal[2][4];
        #pragma unroll
        for (int mt = 0; mt < 2; mt++) {
            int r = wm * 32 + mt * 16 + g;
            fah[mt][0] = Ah[cur][r][t];
            fah[mt][1] = Ah[cur][r + 8][t];
            fah[mt][2] = Ah[cur][r][t + 4];
            fah[mt][3] = Ah[cur][r + 8][t + 4];
            fal[mt][0] = Al[cur][r][t];
            fal[mt][1] = Al[cur][r + 8][t];
            fal[mt][2] = Al[cur][r][t + 4];
            fal[mt][3] = Al[cur][r + 8][t + 4];
        }
        #pragma unroll
        for (int nt = 0; nt < 8; nt++) {
            int cn = wn * 64 + nt * 8 + g;
            u32 bh0 = Bh[cur][t][cn],     bh1 = Bh[cur][t + 4][cn];
            u32 bl0 = Bl[cur][t][cn],     bl1 = Bl[cur][t + 4][cn];
            #pragma unroll
            for (int mt = 0; mt < 2; mt++) {
                mma_bf16(acc[mt][nt], fah[mt], bh0, bh1);
                mma_bf16(acc[mt][nt], fah[mt], bl0, bl1);
                mma_bf16(acc[mt][nt], fal[mt], bh0, bh1);
            }
        }

        if (s + 1 < STAGES) {
            int nxt = cur ^ 1;
            *(uint4*)&Ah[nxt][arow][ah4] = vah;
            *(uint4*)&Al[nxt][arow][ah4] = val;
            *(uint4*)&Bh[nxt][brow][bc4] = vbh;
            *(uint4*)&Bl[nxt][brow][bc4] = vbl;
        }
        __syncthreads();
    }

    // epilogue
    bool hasB = (bn < 3);
    #pragma unroll
    for (int mt = 0; mt < 2; mt++) {
        int row0 = bm * 128 + wm * 32 + mt * 16 + g;
        #pragma unroll
        for (int nt = 0; nt < 8; nt++) {
            int col = bn * 128 + wn * 64 + nt * 8 + 2 * t;
            float bias0 = hasB ? b1[col]     : 0.f;
            float bias1 = hasB ? b1[col + 1] : 0.f;
            float2 v0 = make_float2(acc[mt][nt][0] + bias0, acc[mt][nt][1] + bias1);
            float2 v1 = make_float2(acc[mt][nt][2] + bias0, acc[mt][nt][3] + bias1);
            *(float2*)&g_C[row0 * NOUT + col]       = v0;
            *(float2*)&g_C[(row0 + 8) * NOUT + col] = v1;
        }
    }
}

// ---------------- edge kernel: one warp per node ----------------------------
__global__ __launch_bounds__(256) void edge_kernel(const float* __restrict__ xyz,
                                                   const float* __restrict__ W2,
                                                   const float* __restrict__ b2,
                                                   float* __restrict__ out)
{
    int gwarp = (blockIdx.x * blockDim.x + threadIdx.x) >> 5;
    int lane  = threadIdx.x & 31;
    if (gwarp >= N_PTS) return;

    const float* Ci = g_C + gwarp * NOUT;

    float4 s[3];
    float w2[12][3];
    #pragma unroll
    for (int dn = 0; dn < 3; dn++) {
        int dim0 = lane * 4 + dn * 128;
        float4 a = *(const float4*)(Ci + dim0);           // a_i (has b1)
        float4 b = *(const float4*)(Ci + D_TOK + dim0);   // b_i
        s[dn] = make_float4(a.x - b.x, a.y - b.y, a.z - b.z, a.w - b.w);
        #pragma unroll
        for (int u = 0; u < 4; u++)
            #pragma unroll
            for (int c = 0; c < 3; c++)
                w2[dn * 4 + u][c] = W2[(dim0 + u) * 3 + c];
    }

    float acc0 = 0.f, acc1 = 0.f, acc2 = 0.f;
    #pragma unroll 4
    for (int j = 0; j < KNN_K; j++) {
        int nj = g_knn[gwarp * KNN_K + j];
        const float* Bj = g_C + nj * NOUT + D_TOK;
        #pragma unroll
        for (int dn = 0; dn < 3; dn++) {
            float4 b = *(const float4*)(Bj + lane * 4 + dn * 128);
            float h;
            h = fmaxf(s[dn].x + b.x, 0.f);
            acc0 = fmaf(h, w2[dn*4+0][0], acc0); acc1 = fmaf(h, w2[dn*4+0][1], acc1); acc2 = fmaf(h, w2[dn*4+0][2], acc2);
            h = fmaxf(s[dn].y + b.y, 0.f);
            acc0 = fmaf(h, w2[dn*4+1][0], acc0); acc1 = fmaf(h, w2[dn*4+1][1], acc1); acc2 = fmaf(h, w2[dn*4+1][2], acc2);
            h = fmaxf(s[dn].z + b.z, 0.f);
            acc0 = fmaf(h, w2[dn*4+2][0], acc0); acc1 = fmaf(h, w2[dn*4+2][1], acc1); acc2 = fmaf(h, w2[dn*4+2][2], acc2);
            h = fmaxf(s[dn].w + b.w, 0.f);
            acc0 = fmaf(h, w2[dn*4+3][0], acc0); acc1 = fmaf(h, w2[dn*4+3][1], acc1); acc2 = fmaf(h, w2[dn*4+3][2], acc2);
        }
    }

    #pragma unroll
    for (int off = 16; off > 0; off >>= 1) {
        acc0 += __shfl_down_sync(0xFFFFFFFFu, acc0, off);
        acc1 += __shfl_down_sync(0xFFFFFFFFu, acc1, off);
        acc2 += __shfl_down_sync(0xFFFFFFFFu, acc2, off);
    }

    if (lane == 0) {
        const float inv = 1.f / 16.f;
        out[gwarp * 3 + 0] = xyz[gwarp * 3 + 0] + acc0 * inv + b2[0];
        out[gwarp * 3 + 1] = xyz[gwarp * 3 + 1] + acc1 * inv + b2[1];
        out[gwarp * 3 + 2] = xyz[gwarp * 3 + 2] + acc2 * inv + b2[2];
    }
}

// ---------------- launch ----------------------------------------------------
// gemm at launch index 3 (the one ncu captures) so next round verifies the
// tensor-core prediction directly.
extern "C" void kernel_launch(void* const* d_in, const int* in_sizes, int n_in,
                              void* d_out, int out_size)
{
    const float* xyz   = (const float*)d_in[0];
    const float* token = (const float*)d_in[1];
    const float* W1    = (const float*)d_in[2];
    const float* b1    = (const float*)d_in[3];
    const float* W2    = (const float*)d_in[4];
    const float* b2    = (const float*)d_in[5];
    float* out = (float*)d_out;

    pack_p<<<N_PTS / 256, 256>>>(xyz);
    pack_x<<<N_PTS, 128>>>(token, xyz);
    pack_w<<<KP2, 256>>>(W1);
    gemm_kernel<<<dim3(NOUT / 128, N_PTS / 128), 256>>>(b1);
    knn_warp<<<N_PTS / 8, 256>>>();
    edge_kernel<<<N_PTS / 8, 256>>>(xyz, W2, b2, out);
}